// round 2
// baseline (speedup 1.0000x reference)
#include <cuda_runtime.h>
#include <cuda_bf16.h>
#include <cstdint>

// Problem constants
#define BATCH   8
#define SEQ     2048
#define DMODEL  512
#define DHEAD   64
#define ROWS    (BATCH * SEQ)       // 16384
#define SCALE   0.125f              // 1/sqrt(64)

#define MASK_ELEMS  ((size_t)BATCH * SEQ * SEQ)   // 33554432
#define X_ELEMS     ((size_t)ROWS * DMODEL)       // 8388608
#define W_ELEMS     ((size_t)DMODEL * DHEAD)      // 32768

// Q/K/V scratch (allocation-free: __device__ globals)
__device__ float g_q[ROWS * DHEAD];
__device__ float g_k[ROWS * DHEAD];
__device__ float g_v[ROWS * DHEAD];
__device__ int   g_mask_is_int32;

// ---------------------------------------------------------------------------
// Mask dtype detector: if the mask buffer is int32 {0,1}, every 32-bit word
// is <= 1. If it is byte-packed bools, words pack 4 bools and are almost
// surely > 1 somewhere in the first 4096 words. Deterministic per input.
// ---------------------------------------------------------------------------
__global__ void detect_mask_kernel(const unsigned int* __restrict__ m)
{
    int local = 0;
    #pragma unroll
    for (int i = 0; i < 16; ++i)
        local |= (m[threadIdx.x * 16 + i] > 1u) ? 1 : 0;
    int any = __syncthreads_or(local);
    if (threadIdx.x == 0)
        g_mask_is_int32 = any ? 0 : 1;
}

// ---------------------------------------------------------------------------
// Projection GEMM: out[16384 x 64] = X[16384 x 512] @ W[512 x 64]
// grid = (16384/64, 3); blockIdx.y selects {Q, K, V}
// ---------------------------------------------------------------------------
__global__ __launch_bounds__(256) void proj_kernel(
    const float* __restrict__ x,
    const float* __restrict__ wq,
    const float* __restrict__ wk,
    const float* __restrict__ wv)
{
    __shared__ float sX[64][65];
    __shared__ float sW[64][65];

    const int row0  = blockIdx.x * 64;
    const int which = blockIdx.y;
    const float* w = (which == 0) ? wq : (which == 1) ? wk : wv;
    float* out     = (which == 0) ? g_q : (which == 1) ? g_k : g_v;

    const int tid = threadIdx.x;
    const int ty  = tid >> 4;      // 0..15
    const int tx  = tid & 15;      // 0..15
    const int lr  = tid >> 2;      // 0..63  (loader row)
    const int lc  = (tid & 3) * 16;// 0,16,32,48

    float acc[4][4] = {};

    for (int kb = 0; kb < DMODEL; kb += 64) {
        {
            const float4* src = reinterpret_cast<const float4*>(
                x + (size_t)(row0 + lr) * DMODEL + kb + lc);
            #pragma unroll
            for (int v = 0; v < 4; ++v) {
                float4 f = src[v];
                sX[lr][lc + 4*v + 0] = f.x;
                sX[lr][lc + 4*v + 1] = f.y;
                sX[lr][lc + 4*v + 2] = f.z;
                sX[lr][lc + 4*v + 3] = f.w;
            }
        }
        {
            const float4* src = reinterpret_cast<const float4*>(
                w + (size_t)(kb + lr) * DHEAD + lc);
            #pragma unroll
            for (int v = 0; v < 4; ++v) {
                float4 f = src[v];
                sW[lr][lc + 4*v + 0] = f.x;
                sW[lr][lc + 4*v + 1] = f.y;
                sW[lr][lc + 4*v + 2] = f.z;
                sW[lr][lc + 4*v + 3] = f.w;
            }
        }
        __syncthreads();

        #pragma unroll 16
        for (int k = 0; k < 64; ++k) {
            float xr[4], wc[4];
            #pragma unroll
            for (int r = 0; r < 4; ++r) xr[r] = sX[ty*4 + r][k];
            #pragma unroll
            for (int c = 0; c < 4; ++c) wc[c] = sW[k][tx*4 + c];
            #pragma unroll
            for (int r = 0; r < 4; ++r)
                #pragma unroll
                for (int c = 0; c < 4; ++c)
                    acc[r][c] += xr[r] * wc[c];
        }
        __syncthreads();
    }

    #pragma unroll
    for (int r = 0; r < 4; ++r) {
        float4 v4 = make_float4(acc[r][0], acc[r][1], acc[r][2], acc[r][3]);
        *reinterpret_cast<float4*>(
            out + (size_t)(row0 + ty*4 + r) * DHEAD + tx*4) = v4;
    }
}

// ---------------------------------------------------------------------------
// Flash attention: per (batch, 64-query tile), stream keys in 64-chunks.
// ---------------------------------------------------------------------------
struct AttnSmem {
    float Q[64][65];
    float K[64][65];
    float V[64][65];
    float P[64][65];
    unsigned char M[64][64];
};

__global__ __launch_bounds__(256) void attn_kernel(
    const unsigned char* __restrict__ mask,
    float* __restrict__ out)
{
    extern __shared__ unsigned char smem_raw[];
    AttnSmem& sm = *reinterpret_cast<AttnSmem*>(smem_raw);

    const int b   = blockIdx.y;
    const int i0  = blockIdx.x * 64;
    const int tid = threadIdx.x;
    const int ty  = tid >> 4;
    const int tx  = tid & 15;
    const int lr  = tid >> 2;        // 0..63
    const int lc  = (tid & 3) * 16;  // 0,16,32,48
    const int mask_is_i32 = g_mask_is_int32;

    // load Q tile
    {
        const float4* src = reinterpret_cast<const float4*>(
            g_q + ((size_t)b * SEQ + i0 + lr) * DHEAD + lc);
        #pragma unroll
        for (int v = 0; v < 4; ++v) {
            float4 f = src[v];
            sm.Q[lr][lc + 4*v + 0] = f.x;
            sm.Q[lr][lc + 4*v + 1] = f.y;
            sm.Q[lr][lc + 4*v + 2] = f.z;
            sm.Q[lr][lc + 4*v + 3] = f.w;
        }
    }

    float m_prev[4], lsum[4], o[4][4] = {};
    #pragma unroll
    for (int r = 0; r < 4; ++r) { m_prev[r] = -1e30f; lsum[r] = 0.f; }

    __syncthreads();

    for (int j0 = 0; j0 < SEQ; j0 += 64) {
        // load K chunk, V chunk, mask tile
        {
            const float4* srck = reinterpret_cast<const float4*>(
                g_k + ((size_t)b * SEQ + j0 + lr) * DHEAD + lc);
            const float4* srcv = reinterpret_cast<const float4*>(
                g_v + ((size_t)b * SEQ + j0 + lr) * DHEAD + lc);
            #pragma unroll
            for (int v = 0; v < 4; ++v) {
                float4 fk = srck[v];
                float4 fv = srcv[v];
                sm.K[lr][lc + 4*v + 0] = fk.x;
                sm.K[lr][lc + 4*v + 1] = fk.y;
                sm.K[lr][lc + 4*v + 2] = fk.z;
                sm.K[lr][lc + 4*v + 3] = fk.w;
                sm.V[lr][lc + 4*v + 0] = fv.x;
                sm.V[lr][lc + 4*v + 1] = fv.y;
                sm.V[lr][lc + 4*v + 2] = fv.z;
                sm.V[lr][lc + 4*v + 3] = fv.w;
            }
            // mask tile: rows = query rows (i0+lr), cols = key cols [j0+lc, j0+lc+16)
            const size_t moff = ((size_t)b * SEQ + i0 + lr) * SEQ + j0 + lc;
            if (mask_is_i32) {
                const uint4* mp = reinterpret_cast<const uint4*>(
                    reinterpret_cast<const unsigned int*>(mask) + moff);
                #pragma unroll
                for (int w = 0; w < 4; ++w) {
                    uint4 u = mp[w];
                    sm.M[lr][lc + 4*w + 0] = (unsigned char)(u.x != 0);
                    sm.M[lr][lc + 4*w + 1] = (unsigned char)(u.y != 0);
                    sm.M[lr][lc + 4*w + 2] = (unsigned char)(u.z != 0);
                    sm.M[lr][lc + 4*w + 3] = (unsigned char)(u.w != 0);
                }
            } else {
                const uint4* mp = reinterpret_cast<const uint4*>(mask + moff);
                *reinterpret_cast<uint4*>(&sm.M[lr][lc]) = *mp;
            }
        }
        __syncthreads();

        // S = Q K^T  (4x4 register tile)
        float s[4][4] = {};
        #pragma unroll 16
        for (int k = 0; k < 64; ++k) {
            float q4[4], k4[4];
            #pragma unroll
            for (int r = 0; r < 4; ++r) q4[r] = sm.Q[ty*4 + r][k];
            #pragma unroll
            for (int c = 0; c < 4; ++c) k4[c] = sm.K[tx*4 + c][k];
            #pragma unroll
            for (int r = 0; r < 4; ++r)
                #pragma unroll
                for (int c = 0; c < 4; ++c)
                    s[r][c] += q4[r] * k4[c];
        }

        // mask + scale, online softmax
        #pragma unroll
        for (int r = 0; r < 4; ++r) {
            #pragma unroll
            for (int c = 0; c < 4; ++c) {
                s[r][c] = sm.M[ty*4 + r][tx*4 + c] ? s[r][c] * SCALE : -1e30f;
            }
            float mt = fmaxf(fmaxf(s[r][0], s[r][1]), fmaxf(s[r][2], s[r][3]));
            #pragma unroll
            for (int off = 1; off < 16; off <<= 1)
                mt = fmaxf(mt, __shfl_xor_sync(0xffffffffu, mt, off));
            float m_new = fmaxf(m_prev[r], mt);
            float alpha = __expf(m_prev[r] - m_new);
            float rs = 0.f;
            #pragma unroll
            for (int c = 0; c < 4; ++c) {
                float p = __expf(s[r][c] - m_new);
                s[r][c] = p;
                rs += p;
            }
            #pragma unroll
            for (int off = 1; off < 16; off <<= 1)
                rs += __shfl_xor_sync(0xffffffffu, rs, off);
            lsum[r] = lsum[r] * alpha + rs;
            m_prev[r] = m_new;
            #pragma unroll
            for (int c = 0; c < 4; ++c) o[r][c] *= alpha;
        }

        // stage P
        #pragma unroll
        for (int r = 0; r < 4; ++r)
            #pragma unroll
            for (int c = 0; c < 4; ++c)
                sm.P[ty*4 + r][tx*4 + c] = s[r][c];
        __syncthreads();

        // O += P @ V
        #pragma unroll 16
        for (int k = 0; k < 64; ++k) {
            float p4[4], v4[4];
            #pragma unroll
            for (int r = 0; r < 4; ++r) p4[r] = sm.P[ty*4 + r][k];
            #pragma unroll
            for (int c = 0; c < 4; ++c) v4[c] = sm.V[k][tx*4 + c];
            #pragma unroll
            for (int r = 0; r < 4; ++r)
                #pragma unroll
                for (int c = 0; c < 4; ++c)
                    o[r][c] += p4[r] * v4[c];
        }
        __syncthreads();
    }

    // epilogue: normalize, write out
    #pragma unroll
    for (int r = 0; r < 4; ++r) {
        float inv = 1.0f / lsum[r];
        float4 v4 = make_float4(o[r][0]*inv, o[r][1]*inv, o[r][2]*inv, o[r][3]*inv);
        *reinterpret_cast<float4*>(
            out + ((size_t)b * SEQ + i0 + ty*4 + r) * DHEAD + tx*4) = v4;
    }
}

// ---------------------------------------------------------------------------
// kernel_launch — graph-capturable, allocation-free.
// Inputs mapped by element count (robust to metadata ordering):
//   mask = 33554432 elems, x = 8388608 elems, wk/wq/wv = 32768 elems each
//   (relative order of wk,wq,wv is the same in dict and alphabetical order)
// ---------------------------------------------------------------------------
extern "C" void kernel_launch(void* const* d_in, const int* in_sizes, int n_in,
                              void* d_out, int out_size)
{
    const void*  mask = nullptr;
    const float* x    = nullptr;
    const float* wbuf[3] = {nullptr, nullptr, nullptr};
    int nw = 0;

    for (int i = 0; i < n_in; ++i) {
        size_t sz = (size_t)in_sizes[i];
        if (sz == MASK_ELEMS)      mask = d_in[i];
        else if (sz == X_ELEMS)    x = (const float*)d_in[i];
        else if (sz == W_ELEMS && nw < 3) wbuf[nw++] = (const float*)d_in[i];
    }
    const float* wk = wbuf[0];
    const float* wq = wbuf[1];
    const float* wv = wbuf[2];
    float* out = (float*)d_out;

    // 0) detect mask dtype (int32 vs byte bools)
    detect_mask_kernel<<<1, 256>>>((const unsigned int*)mask);

    // 1) projections: Q, K, V
    proj_kernel<<<dim3(ROWS / 64, 3), 256>>>(x, wq, wk, wv);

    // 2) attention
    cudaFuncSetAttribute(attn_kernel,
                         cudaFuncAttributeMaxDynamicSharedMemorySize,
                         (int)sizeof(AttnSmem));
    attn_kernel<<<dim3(SEQ / 64, BATCH), 256, sizeof(AttnSmem)>>>(
        (const unsigned char*)mask, out);
}

// round 3
// speedup vs baseline: 1.9606x; 1.9606x over previous
#include <cuda_runtime.h>
#include <cstdint>

#define BATCH   8
#define SEQ     2048
#define DMODEL  512
#define DHEAD   64
#define ROWS    (BATCH * SEQ)
#define SCALE   0.125f
#define LD      68           // smem row stride (floats) -> conflict-free frags

#define MASK_ELEMS  ((size_t)BATCH * SEQ * SEQ)   // 33554432
#define X_ELEMS     ((size_t)ROWS * DMODEL)       // 8388608
#define W_ELEMS     ((size_t)DMODEL * DHEAD)      // 32768

__device__ float g_q[ROWS * DHEAD];
__device__ float g_k[ROWS * DHEAD];
__device__ float g_v[ROWS * DHEAD];

// round-to-nearest tf32 (unbiased; raw-bit truncation would bias dot products)
__device__ __forceinline__ float tf32r(float x) {
    unsigned u;
    asm("cvt.rna.tf32.f32 %0, %1;" : "=r"(u) : "f"(x));
    return __uint_as_float(u);
}

__device__ __forceinline__ void mma8(float* d,
    unsigned a0, unsigned a1, unsigned a2, unsigned a3,
    unsigned b0, unsigned b1)
{
    asm volatile(
        "mma.sync.aligned.m16n8k8.row.col.f32.tf32.tf32.f32 "
        "{%0,%1,%2,%3},{%4,%5,%6,%7},{%8,%9},{%0,%1,%2,%3};"
        : "+f"(d[0]), "+f"(d[1]), "+f"(d[2]), "+f"(d[3])
        : "r"(a0), "r"(a1), "r"(a2), "r"(a3), "r"(b0), "r"(b1));
}

// ---------------------------------------------------------------------------
// Projection: out[16384x64] = X[16384x512] @ W[512x64], tf32 mma.
// grid (128, 3): 128-row tiles, y selects {Q,K,V}. 8 warps x 16 rows.
// ---------------------------------------------------------------------------
__global__ __launch_bounds__(256) void proj_kernel(
    const float* __restrict__ x,
    const float* __restrict__ wq,
    const float* __restrict__ wk,
    const float* __restrict__ wv)
{
    extern __shared__ float psm[];
    float* sX = psm;              // 128*LD
    float* sW = psm + 128 * LD;   // 64*LD

    const int row0  = blockIdx.x * 128;
    const int which = blockIdx.y;
    const float* w = (which == 0) ? wq : (which == 1) ? wk : wv;
    float* outp    = (which == 0) ? g_q : (which == 1) ? g_k : g_v;

    const int tid  = threadIdx.x;
    const int warp = tid >> 5, lane = tid & 31;
    const int g = lane >> 2, tg = lane & 3;
    const int r0 = warp * 16;

    const int xr = tid >> 1, xc = (tid & 1) * 32;
    const int wr = tid >> 2, wc = (tid & 3) * 16;

    float o[8][4];
    #pragma unroll
    for (int nt = 0; nt < 8; ++nt)
        #pragma unroll
        for (int i = 0; i < 4; ++i) o[nt][i] = 0.f;

    for (int kb = 0; kb < DMODEL; kb += 64) {
        const float4* xs = reinterpret_cast<const float4*>(
            x + (size_t)(row0 + xr) * DMODEL + kb + xc);
        #pragma unroll
        for (int v = 0; v < 8; ++v) {
            float4 f = xs[v];
            sX[xr*LD + xc + 4*v + 0] = tf32r(f.x);
            sX[xr*LD + xc + 4*v + 1] = tf32r(f.y);
            sX[xr*LD + xc + 4*v + 2] = tf32r(f.z);
            sX[xr*LD + xc + 4*v + 3] = tf32r(f.w);
        }
        const float4* ws = reinterpret_cast<const float4*>(
            w + (size_t)(kb + wr) * DHEAD + wc);
        #pragma unroll
        for (int v = 0; v < 4; ++v) {
            float4 f = ws[v];
            sW[wr*LD + wc + 4*v + 0] = tf32r(f.x);
            sW[wr*LD + wc + 4*v + 1] = tf32r(f.y);
            sW[wr*LD + wc + 4*v + 2] = tf32r(f.z);
            sW[wr*LD + wc + 4*v + 3] = tf32r(f.w);
        }
        __syncthreads();

        const unsigned* Xu = reinterpret_cast<const unsigned*>(sX);
        const unsigned* Wu = reinterpret_cast<const unsigned*>(sW);
        #pragma unroll
        for (int kk = 0; kk < 8; ++kk) {
            unsigned a0 = Xu[(r0+g)*LD   + kk*8 + tg];
            unsigned a1 = Xu[(r0+g+8)*LD + kk*8 + tg];
            unsigned a2 = Xu[(r0+g)*LD   + kk*8 + tg + 4];
            unsigned a3 = Xu[(r0+g+8)*LD + kk*8 + tg + 4];
            #pragma unroll
            for (int nt = 0; nt < 8; ++nt) {
                unsigned b0 = Wu[(kk*8+tg)*LD   + nt*8 + g];
                unsigned b1 = Wu[(kk*8+tg+4)*LD + nt*8 + g];
                mma8(o[nt], a0, a1, a2, a3, b0, b1);
            }
        }
        __syncthreads();
    }

    #pragma unroll
    for (int nt = 0; nt < 8; ++nt) {
        int col = nt*8 + 2*tg;
        *reinterpret_cast<float2*>(outp + (size_t)(row0 + r0 + g) * DHEAD + col)
            = make_float2(o[nt][0], o[nt][1]);
        *reinterpret_cast<float2*>(outp + (size_t)(row0 + r0 + g + 8) * DHEAD + col)
            = make_float2(o[nt][2], o[nt][3]);
    }
}

// ---------------------------------------------------------------------------
// Flash attention, tf32 mma. 128-query tile x 64-key chunks. 8 warps,
// each warp owns 16 full rows -> softmax is quad-local (shfl xor 1,2).
// K/V/mask register-prefetched one chunk ahead.
// ---------------------------------------------------------------------------
struct AttnSmem {
    float    Q[128 * LD];
    float    K[64 * LD];
    float    V[64 * LD];
    float    P[128 * LD];
    unsigned M[128 * 16];   // 128 rows x 64 mask bytes
};

__global__ __launch_bounds__(256) void attn_kernel(
    const unsigned char* __restrict__ mask,
    float* __restrict__ out)
{
    extern __shared__ unsigned char smraw[];
    AttnSmem& sm = *reinterpret_cast<AttnSmem*>(smraw);

    const int b  = blockIdx.y;
    const int i0 = blockIdx.x * 128;
    const int tid  = threadIdx.x;
    const int warp = tid >> 5, lane = tid & 31;
    const int g = lane >> 2, tg = lane & 3;
    const int r0 = warp * 16;

    // ---- mask dtype detection (int32 {0,1} vs byte bools), block-local ----
    unsigned local = 0;
    {
        const unsigned* mw = reinterpret_cast<const unsigned*>(mask);
        #pragma unroll
        for (int i = 0; i < 4; ++i)
            local |= (mw[tid*4 + i] > 1u) ? 1u : 0u;
    }
    const bool mask_bytes = (__syncthreads_or((int)local) != 0);

    // ---- Q tile load (tf32-rounded) ----
    {
        const int qr = tid >> 1, qc = (tid & 1) * 32;
        const float4* qs = reinterpret_cast<const float4*>(
            g_q + ((size_t)b * SEQ + i0 + qr) * DHEAD + qc);
        #pragma unroll
        for (int v = 0; v < 8; ++v) {
            float4 f = qs[v];
            sm.Q[qr*LD + qc + 4*v + 0] = tf32r(f.x);
            sm.Q[qr*LD + qc + 4*v + 1] = tf32r(f.y);
            sm.Q[qr*LD + qc + 4*v + 2] = tf32r(f.z);
            sm.Q[qr*LD + qc + 4*v + 3] = tf32r(f.w);
        }
    }

    const int kr = tid >> 2, kc = (tid & 3) * 16;   // K/V loader: 64 rows x 16 f
    const int mr = tid >> 1, mc = (tid & 1) * 32;   // mask loader: 128 rows x 32 cols

    float4 kreg[4], vreg[4];
    unsigned mreg[8];

    // prefetch helpers (expanded inline below)
    #define LOAD_KVM(J0)                                                        \
    do {                                                                        \
        const float4* ksrc = reinterpret_cast<const float4*>(                   \
            g_k + ((size_t)b * SEQ + (J0) + kr) * DHEAD + kc);                  \
        const float4* vsrc = reinterpret_cast<const float4*>(                   \
            g_v + ((size_t)b * SEQ + (J0) + kr) * DHEAD + kc);                  \
        _Pragma("unroll")                                                       \
        for (int v = 0; v < 4; ++v) { kreg[v] = ksrc[v]; vreg[v] = vsrc[v]; }   \
        if (mask_bytes) {                                                       \
            const uint4* ms = reinterpret_cast<const uint4*>(                   \
                mask + ((size_t)b * SEQ + i0 + mr) * SEQ + (J0) + mc);          \
            uint4 u0 = ms[0], u1 = ms[1];                                       \
            mreg[0]=u0.x; mreg[1]=u0.y; mreg[2]=u0.z; mreg[3]=u0.w;             \
            mreg[4]=u1.x; mreg[5]=u1.y; mreg[6]=u1.z; mreg[7]=u1.w;             \
        } else {                                                                \
            const uint4* ms = reinterpret_cast<const uint4*>(                   \
                reinterpret_cast<const unsigned*>(mask)                         \
                + ((size_t)b * SEQ + i0 + mr) * SEQ + (J0) + mc);               \
            _Pragma("unroll")                                                   \
            for (int w8 = 0; w8 < 8; ++w8) {                                    \
                uint4 u = ms[w8];                                               \
                mreg[w8] = (unsigned)(u.x != 0) | ((unsigned)(u.y != 0) << 8)   \
                         | ((unsigned)(u.z != 0) << 16)                         \
                         | ((unsigned)(u.w != 0) << 24);                        \
            }                                                                   \
        }                                                                       \
    } while (0)

    #define STORE_KVM()                                                         \
    do {                                                                        \
        _Pragma("unroll")                                                       \
        for (int v = 0; v < 4; ++v) {                                           \
            sm.K[kr*LD + kc + 4*v + 0] = tf32r(kreg[v].x);                      \
            sm.K[kr*LD + kc + 4*v + 1] = tf32r(kreg[v].y);                      \
            sm.K[kr*LD + kc + 4*v + 2] = tf32r(kreg[v].z);                      \
            sm.K[kr*LD + kc + 4*v + 3] = tf32r(kreg[v].w);                      \
            sm.V[kr*LD + kc + 4*v + 0] = tf32r(vreg[v].x);                      \
            sm.V[kr*LD + kc + 4*v + 1] = tf32r(vreg[v].y);                      \
            sm.V[kr*LD + kc + 4*v + 2] = tf32r(vreg[v].z);                      \
            sm.V[kr*LD + kc + 4*v + 3] = tf32r(vreg[v].w);                      \
        }                                                                       \
        _Pragma("unroll")                                                       \
        for (int w8 = 0; w8 < 8; ++w8)                                          \
            sm.M[mr*16 + (mc >> 2) + w8] = mreg[w8];                            \
    } while (0)

    // prologue: chunk 0
    LOAD_KVM(0);
    STORE_KVM();
    __syncthreads();

    float m_prev[2] = {-1e30f, -1e30f};
    float lsum[2]   = {0.f, 0.f};
    float o[8][4];
    #pragma unroll
    for (int nt = 0; nt < 8; ++nt)
        #pragma unroll
        for (int i = 0; i < 4; ++i) o[nt][i] = 0.f;

    for (int c = 0; c < 32; ++c) {
        if (c + 1 < 32) LOAD_KVM((c + 1) * 64);

        // ---- S = Q K^T ----
        float s[8][4];
        #pragma unroll
        for (int nt = 0; nt < 8; ++nt)
            #pragma unroll
            for (int i = 0; i < 4; ++i) s[nt][i] = 0.f;

        const unsigned* Qu = reinterpret_cast<const unsigned*>(sm.Q);
        const unsigned* Ku = reinterpret_cast<const unsigned*>(sm.K);
        #pragma unroll
        for (int kk = 0; kk < 8; ++kk) {
            unsigned a0 = Qu[(r0+g)*LD   + kk*8 + tg];
            unsigned a1 = Qu[(r0+g+8)*LD + kk*8 + tg];
            unsigned a2 = Qu[(r0+g)*LD   + kk*8 + tg + 4];
            unsigned a3 = Qu[(r0+g+8)*LD + kk*8 + tg + 4];
            #pragma unroll
            for (int nt = 0; nt < 8; ++nt) {
                unsigned b0 = Ku[(nt*8+g)*LD + kk*8 + tg];
                unsigned b1 = Ku[(nt*8+g)*LD + kk*8 + tg + 4];
                mma8(s[nt], a0, a1, a2, a3, b0, b1);
            }
        }

        // ---- mask + online softmax (rows r0+g and r0+g+8) ----
        const unsigned char* Mb = reinterpret_cast<const unsigned char*>(sm.M);
        float mxA = -1e30f, mxB = -1e30f;
        #pragma unroll
        for (int nt = 0; nt < 8; ++nt) {
            int col = nt*8 + 2*tg;
            unsigned char ma0 = Mb[(r0+g)*64 + col];
            unsigned char ma1 = Mb[(r0+g)*64 + col + 1];
            unsigned char mb0 = Mb[(r0+g+8)*64 + col];
            unsigned char mb1 = Mb[(r0+g+8)*64 + col + 1];
            s[nt][0] = ma0 ? s[nt][0] * SCALE : -1e30f;
            s[nt][1] = ma1 ? s[nt][1] * SCALE : -1e30f;
            s[nt][2] = mb0 ? s[nt][2] * SCALE : -1e30f;
            s[nt][3] = mb1 ? s[nt][3] * SCALE : -1e30f;
            mxA = fmaxf(mxA, fmaxf(s[nt][0], s[nt][1]));
            mxB = fmaxf(mxB, fmaxf(s[nt][2], s[nt][3]));
        }
        mxA = fmaxf(mxA, __shfl_xor_sync(0xffffffffu, mxA, 1));
        mxA = fmaxf(mxA, __shfl_xor_sync(0xffffffffu, mxA, 2));
        mxB = fmaxf(mxB, __shfl_xor_sync(0xffffffffu, mxB, 1));
        mxB = fmaxf(mxB, __shfl_xor_sync(0xffffffffu, mxB, 2));

        float mnA = fmaxf(m_prev[0], mxA);
        float mnB = fmaxf(m_prev[1], mxB);
        float alA = __expf(m_prev[0] - mnA);
        float alB = __expf(m_prev[1] - mnB);

        float rsA = 0.f, rsB = 0.f;
        #pragma unroll
        for (int nt = 0; nt < 8; ++nt) {
            s[nt][0] = __expf(s[nt][0] - mnA);
            s[nt][1] = __expf(s[nt][1] - mnA);
            s[nt][2] = __expf(s[nt][2] - mnB);
            s[nt][3] = __expf(s[nt][3] - mnB);
            rsA += s[nt][0] + s[nt][1];
            rsB += s[nt][2] + s[nt][3];
        }
        rsA += __shfl_xor_sync(0xffffffffu, rsA, 1);
        rsA += __shfl_xor_sync(0xffffffffu, rsA, 2);
        rsB += __shfl_xor_sync(0xffffffffu, rsB, 1);
        rsB += __shfl_xor_sync(0xffffffffu, rsB, 2);

        lsum[0] = lsum[0] * alA + rsA;
        lsum[1] = lsum[1] * alB + rsB;
        m_prev[0] = mnA;
        m_prev[1] = mnB;

        #pragma unroll
        for (int nt = 0; nt < 8; ++nt) {
            o[nt][0] *= alA; o[nt][1] *= alA;
            o[nt][2] *= alB; o[nt][3] *= alB;
        }

        // ---- stage P (own rows only -> syncwarp suffices) ----
        #pragma unroll
        for (int nt = 0; nt < 8; ++nt) {
            int col = nt*8 + 2*tg;
            *reinterpret_cast<float2*>(&sm.P[(r0+g)*LD + col])
                = make_float2(tf32r(s[nt][0]), tf32r(s[nt][1]));
            *reinterpret_cast<float2*>(&sm.P[(r0+g+8)*LD + col])
                = make_float2(tf32r(s[nt][2]), tf32r(s[nt][3]));
        }
        __syncwarp();

        // ---- O += P V ----
        const unsigned* Pu = reinterpret_cast<const unsigned*>(sm.P);
        const unsigned* Vu = reinterpret_cast<const unsigned*>(sm.V);
        #pragma unroll
        for (int kk = 0; kk < 8; ++kk) {
            unsigned a0 = Pu[(r0+g)*LD   + kk*8 + tg];
            unsigned a1 = Pu[(r0+g+8)*LD + kk*8 + tg];
            unsigned a2 = Pu[(r0+g)*LD   + kk*8 + tg + 4];
            unsigned a3 = Pu[(r0+g+8)*LD + kk*8 + tg + 4];
            #pragma unroll
            for (int nt = 0; nt < 8; ++nt) {
                unsigned b0 = Vu[(kk*8+tg)*LD   + nt*8 + g];
                unsigned b1 = Vu[(kk*8+tg+4)*LD + nt*8 + g];
                mma8(o[nt], a0, a1, a2, a3, b0, b1);
            }
        }

        __syncthreads();                 // all K/V/M reads done
        if (c + 1 < 32) STORE_KVM();     // write next chunk
        __syncthreads();                 // smem ready
    }

    // ---- epilogue ----
    float iA = 1.f / lsum[0];
    float iB = 1.f / lsum[1];
    #pragma unroll
    for (int nt = 0; nt < 8; ++nt) {
        int col = nt*8 + 2*tg;
        *reinterpret_cast<float2*>(
            out + ((size_t)b * SEQ + i0 + r0 + g) * DHEAD + col)
            = make_float2(o[nt][0] * iA, o[nt][1] * iA);
        *reinterpret_cast<float2*>(
            out + ((size_t)b * SEQ + i0 + r0 + g + 8) * DHEAD + col)
            = make_float2(o[nt][2] * iB, o[nt][3] * iB);
    }
    #undef LOAD_KVM
    #undef STORE_KVM
}

// ---------------------------------------------------------------------------
// kernel_launch — graph-capturable, allocation-free.
// Inputs mapped by element count: mask=33554432, x=8388608, wk/wq/wv=32768
// (relative order of the three W's identical under dict or sorted order).
// ---------------------------------------------------------------------------
extern "C" void kernel_launch(void* const* d_in, const int* in_sizes, int n_in,
                              void* d_out, int out_size)
{
    const void*  mask = nullptr;
    const float* x    = nullptr;
    const float* wbuf[3] = {nullptr, nullptr, nullptr};
    int nw = 0;

    for (int i = 0; i < n_in; ++i) {
        size_t sz = (size_t)in_sizes[i];
        if (sz == MASK_ELEMS)      mask = d_in[i];
        else if (sz == X_ELEMS)    x = (const float*)d_in[i];
        else if (sz == W_ELEMS && nw < 3) wbuf[nw++] = (const float*)d_in[i];
    }
    const float* wk = wbuf[0];
    const float* wq = wbuf[1];
    const float* wv = wbuf[2];
    float* out = (float*)d_out;

    const int proj_smem = (128 * LD + 64 * LD) * (int)sizeof(float);
    cudaFuncSetAttribute(proj_kernel,
                         cudaFuncAttributeMaxDynamicSharedMemorySize, proj_smem);
    proj_kernel<<<dim3(ROWS / 128, 3), 256, proj_smem>>>(x, wq, wk, wv);

    cudaFuncSetAttribute(attn_kernel,
                         cudaFuncAttributeMaxDynamicSharedMemorySize,
                         (int)sizeof(AttnSmem));
    attn_kernel<<<dim3(SEQ / 128, BATCH), 256, sizeof(AttnSmem)>>>(
        (const unsigned char*)mask, out);
}

// round 4
// speedup vs baseline: 2.9094x; 1.4839x over previous
#include <cuda_runtime.h>
#include <cuda_fp16.h>
#include <cstdint>

#define BATCH   8
#define SEQ     2048
#define DMODEL  512
#define DHEAD   64
#define ROWS    (BATCH * SEQ)
#define SCALE   0.125f
#define LDH     72      // smem stride in halves
#define LDW     36      // smem stride in 32-bit words
#define MLD     72      // mask smem stride in bytes

#define MASK_ELEMS  ((size_t)BATCH * SEQ * SEQ)
#define X_ELEMS     ((size_t)ROWS * DMODEL)
#define W_ELEMS     ((size_t)DMODEL * DHEAD)

__device__ __half g_q[ROWS * DHEAD];
__device__ __half g_k[ROWS * DHEAD];
__device__ __half g_v[ROWS * DHEAD];

__device__ __forceinline__ unsigned h2u(__half2 h) {
    return *reinterpret_cast<unsigned*>(&h);
}
__device__ __forceinline__ unsigned packf2(float a, float b) {
    __half2 h = __float22half2_rn(make_float2(a, b));
    return *reinterpret_cast<unsigned*>(&h);
}

__device__ __forceinline__ void hmma(float* d,
    unsigned a0, unsigned a1, unsigned a2, unsigned a3,
    unsigned b0, unsigned b1)
{
    asm volatile(
        "mma.sync.aligned.m16n8k16.row.col.f32.f16.f16.f32 "
        "{%0,%1,%2,%3},{%4,%5,%6,%7},{%8,%9},{%0,%1,%2,%3};"
        : "+f"(d[0]), "+f"(d[1]), "+f"(d[2]), "+f"(d[3])
        : "r"(a0), "r"(a1), "r"(a2), "r"(a3), "r"(b0), "r"(b1));
}

// ---------------------------------------------------------------------------
// Projection: g_{q,k,v}[16384x64] (half) = X[16384x512] @ W[512x64], f16 mma.
// grid (128, 3). 8 warps x 16 rows. W transposed into smem per 64-k block.
// ---------------------------------------------------------------------------
__global__ __launch_bounds__(256) void proj_kernel(
    const float* __restrict__ x,
    const float* __restrict__ wq,
    const float* __restrict__ wk,
    const float* __restrict__ wv)
{
    extern __shared__ __half psm[];
    __half* sX  = psm;                 // [128][LDH]
    __half* sWT = psm + 128 * LDH;     // [64 n][LDH] (k-local cols)

    const int row0  = blockIdx.x * 128;
    const int which = blockIdx.y;
    const float* w = (which == 0) ? wq : (which == 1) ? wk : wv;
    __half* outp   = (which == 0) ? g_q : (which == 1) ? g_k : g_v;

    const int tid  = threadIdx.x;
    const int warp = tid >> 5, lane = tid & 31;
    const int g = lane >> 2, tg = lane & 3;
    const int r0 = warp * 16;

    const int xr = tid >> 1, xc = (tid & 1) * 32;  // X loader
    const int wr = tid >> 2, tg4 = tid & 3;        // W loader

    float o[8][4];
    #pragma unroll
    for (int nt = 0; nt < 8; ++nt)
        #pragma unroll
        for (int i = 0; i < 4; ++i) o[nt][i] = 0.f;

    for (int kb = 0; kb < DMODEL; kb += 64) {
        // X tile -> half smem
        const float4* xs = reinterpret_cast<const float4*>(
            x + (size_t)(row0 + xr) * DMODEL + kb + xc);
        #pragma unroll
        for (int v = 0; v < 8; ++v) {
            float4 f = xs[v];
            uint2 u;
            u.x = h2u(__float22half2_rn(make_float2(f.x, f.y)));
            u.y = h2u(__float22half2_rn(make_float2(f.z, f.w)));
            *reinterpret_cast<uint2*>(&sX[xr * LDH + xc + 4 * v]) = u;
        }
        // W block transposed: sWT[n][k_local]
        #pragma unroll
        for (int i = 0; i < 8; ++i) {
            int n = 2 * tg4 + 8 * i;
            float2 f = *reinterpret_cast<const float2*>(
                w + (size_t)(kb + wr) * DHEAD + n);
            sWT[n * LDH + wr]       = __float2half(f.x);
            sWT[(n + 1) * LDH + wr] = __float2half(f.y);
        }
        __syncthreads();

        const unsigned* Xw = reinterpret_cast<const unsigned*>(sX);
        const unsigned* Ww = reinterpret_cast<const unsigned*>(sWT);
        #pragma unroll
        for (int kt = 0; kt < 4; ++kt) {
            unsigned a0 = Xw[(r0 + g) * LDW + kt * 8 + tg];
            unsigned a1 = Xw[(r0 + g + 8) * LDW + kt * 8 + tg];
            unsigned a2 = Xw[(r0 + g) * LDW + kt * 8 + tg + 4];
            unsigned a3 = Xw[(r0 + g + 8) * LDW + kt * 8 + tg + 4];
            #pragma unroll
            for (int nt = 0; nt < 8; ++nt) {
                unsigned b0 = Ww[(nt * 8 + g) * LDW + kt * 8 + tg];
                unsigned b1 = Ww[(nt * 8 + g) * LDW + kt * 8 + tg + 4];
                hmma(o[nt], a0, a1, a2, a3, b0, b1);
            }
        }
        __syncthreads();
    }

    #pragma unroll
    for (int nt = 0; nt < 8; ++nt) {
        int col = nt * 8 + 2 * tg;
        *reinterpret_cast<unsigned*>(
            outp + (size_t)(row0 + r0 + g) * DHEAD + col) = packf2(o[nt][0], o[nt][1]);
        *reinterpret_cast<unsigned*>(
            outp + (size_t)(row0 + r0 + g + 8) * DHEAD + col) = packf2(o[nt][2], o[nt][3]);
    }
}

// ---------------------------------------------------------------------------
// Flash attention, f16 mma, FA2-style P reuse (no smem round trip).
// 128-query tile, 64-key chunks, double-buffered K/VT/M smem.
// ---------------------------------------------------------------------------
struct AttnSmem {
    __half        Q[128 * LDH];
    __half        K[2][64 * LDH];
    __half        VT[2][64 * LDH];      // VT[d][j]
    unsigned char M[2][128 * MLD];
};

__global__ __launch_bounds__(256) void attn_kernel(
    const unsigned char* __restrict__ mask,
    float* __restrict__ out)
{
    extern __shared__ unsigned char smraw[];
    AttnSmem& sm = *reinterpret_cast<AttnSmem*>(smraw);

    const int b  = blockIdx.y;
    const int i0 = blockIdx.x * 128;
    const int tid  = threadIdx.x;
    const int warp = tid >> 5, lane = tid & 31;
    const int g = lane >> 2, tg = lane & 3;
    const int r0 = warp * 16;

    // ---- mask dtype detection ----
    unsigned local = 0;
    {
        const unsigned* mw = reinterpret_cast<const unsigned*>(mask);
        #pragma unroll
        for (int i = 0; i < 4; ++i)
            local |= (mw[tid * 4 + i] > 1u) ? 1u : 0u;
    }
    const bool mask_bytes = (__syncthreads_or((int)local) != 0);

    // ---- Q tile -> smem (half, stride LDH) ----
    {
        const int qr = tid >> 1, qc = (tid & 1) * 32;
        const uint4* qs = reinterpret_cast<const uint4*>(
            g_q + ((size_t)b * SEQ + i0 + qr) * DHEAD + qc);
        #pragma unroll
        for (int v = 0; v < 4; ++v)
            *reinterpret_cast<uint4*>(&sm.Q[qr * LDH + qc + 8 * v]) = qs[v];
    }

    // loaders
    const int kr  = tid >> 2, kc  = (tid & 3) * 16;  // K: row, 16-half block
    const int jr  = tid >> 2, tg4 = tid & 3;         // V: row j, d pairs
    const int mr  = tid >> 1, mc  = (tid & 1) * 32;  // mask: row, 32-col block

    uint4    ku[2];
    unsigned vv[8];
    unsigned mreg[8];

    #define LOAD_KVM(J0)                                                        \
    do {                                                                        \
        const uint4* ks = reinterpret_cast<const uint4*>(                       \
            g_k + ((size_t)b * SEQ + (J0) + kr) * DHEAD + kc);                  \
        ku[0] = ks[0]; ku[1] = ks[1];                                           \
        const __half* vrow = g_v + ((size_t)b * SEQ + (J0) + jr) * DHEAD;       \
        _Pragma("unroll")                                                       \
        for (int i = 0; i < 8; ++i)                                             \
            vv[i] = *reinterpret_cast<const unsigned*>(vrow + 2 * tg4 + 8 * i); \
        if (mask_bytes) {                                                       \
            const uint4* ms = reinterpret_cast<const uint4*>(                   \
                mask + ((size_t)b * SEQ + i0 + mr) * SEQ + (J0) + mc);          \
            uint4 u0 = ms[0], u1 = ms[1];                                       \
            mreg[0]=u0.x; mreg[1]=u0.y; mreg[2]=u0.z; mreg[3]=u0.w;             \
            mreg[4]=u1.x; mreg[5]=u1.y; mreg[6]=u1.z; mreg[7]=u1.w;             \
        } else {                                                                \
            const uint4* ms = reinterpret_cast<const uint4*>(                   \
                reinterpret_cast<const unsigned*>(mask)                         \
                + ((size_t)b * SEQ + i0 + mr) * SEQ + (J0) + mc);               \
            _Pragma("unroll")                                                   \
            for (int w8 = 0; w8 < 8; ++w8) {                                    \
                uint4 u = ms[w8];                                               \
                mreg[w8] = (unsigned)(u.x != 0) | ((unsigned)(u.y != 0) << 8)   \
                         | ((unsigned)(u.z != 0) << 16)                         \
                         | ((unsigned)(u.w != 0) << 24);                        \
            }                                                                   \
        }                                                                       \
    } while (0)

    #define STORE_KVM(BUF)                                                      \
    do {                                                                        \
        *reinterpret_cast<uint4*>(&sm.K[BUF][kr * LDH + kc])     = ku[0];       \
        *reinterpret_cast<uint4*>(&sm.K[BUF][kr * LDH + kc + 8]) = ku[1];       \
        _Pragma("unroll")                                                       \
        for (int i = 0; i < 8; ++i) {                                           \
            __half2 h = *reinterpret_cast<__half2*>(&vv[i]);                    \
            int d = 2 * tg4 + 8 * i;                                            \
            sm.VT[BUF][d * LDH + jr]       = __low2half(h);                     \
            sm.VT[BUF][(d + 1) * LDH + jr] = __high2half(h);                    \
        }                                                                       \
        _Pragma("unroll")                                                       \
        for (int w8 = 0; w8 < 4; ++w8)                                          \
            *reinterpret_cast<uint2*>(&sm.M[BUF][mr * MLD + mc + 8 * w8])       \
                = make_uint2(mreg[2 * w8], mreg[2 * w8 + 1]);                   \
    } while (0)

    LOAD_KVM(0);
    STORE_KVM(0);
    __syncthreads();

    // ---- Q fragments: held in registers for the whole kernel ----
    unsigned qf[4][4];
    {
        const unsigned* Qw = reinterpret_cast<const unsigned*>(sm.Q);
        #pragma unroll
        for (int kt = 0; kt < 4; ++kt) {
            qf[kt][0] = Qw[(r0 + g) * LDW + kt * 8 + tg];
            qf[kt][1] = Qw[(r0 + g + 8) * LDW + kt * 8 + tg];
            qf[kt][2] = Qw[(r0 + g) * LDW + kt * 8 + tg + 4];
            qf[kt][3] = Qw[(r0 + g + 8) * LDW + kt * 8 + tg + 4];
        }
    }

    float m_prev[2] = {-1e30f, -1e30f};
    float lsum[2]   = {0.f, 0.f};
    float o[8][4];
    #pragma unroll
    for (int nt = 0; nt < 8; ++nt)
        #pragma unroll
        for (int i = 0; i < 4; ++i) o[nt][i] = 0.f;

    for (int c = 0; c < 32; ++c) {
        const int cur = c & 1;
        if (c + 1 < 32) LOAD_KVM((c + 1) * 64);

        // ---- S = Q K^T ----
        float s[8][4];
        #pragma unroll
        for (int nt = 0; nt < 8; ++nt)
            #pragma unroll
            for (int i = 0; i < 4; ++i) s[nt][i] = 0.f;

        {
            const unsigned* Kw = reinterpret_cast<const unsigned*>(sm.K[cur]);
            #pragma unroll
            for (int kt = 0; kt < 4; ++kt) {
                #pragma unroll
                for (int nt = 0; nt < 8; ++nt) {
                    unsigned b0 = Kw[(nt * 8 + g) * LDW + kt * 8 + tg];
                    unsigned b1 = Kw[(nt * 8 + g) * LDW + kt * 8 + tg + 4];
                    hmma(s[nt], qf[kt][0], qf[kt][1], qf[kt][2], qf[kt][3], b0, b1);
                }
            }
        }

        // ---- mask + online softmax ----
        {
            const unsigned char* Mb = sm.M[cur];
            float mxA = -1e30f, mxB = -1e30f;
            #pragma unroll
            for (int nt = 0; nt < 8; ++nt) {
                int col = nt * 8 + 2 * tg;
                unsigned wA = *reinterpret_cast<const unsigned short*>(
                    &Mb[(r0 + g) * MLD + col]);
                unsigned wB = *reinterpret_cast<const unsigned short*>(
                    &Mb[(r0 + g + 8) * MLD + col]);
                s[nt][0] = (wA & 0xffu)  ? s[nt][0] * SCALE : -1e30f;
                s[nt][1] = (wA >> 8)     ? s[nt][1] * SCALE : -1e30f;
                s[nt][2] = (wB & 0xffu)  ? s[nt][2] * SCALE : -1e30f;
                s[nt][3] = (wB >> 8)     ? s[nt][3] * SCALE : -1e30f;
                mxA = fmaxf(mxA, fmaxf(s[nt][0], s[nt][1]));
                mxB = fmaxf(mxB, fmaxf(s[nt][2], s[nt][3]));
            }
            mxA = fmaxf(mxA, __shfl_xor_sync(0xffffffffu, mxA, 1));
            mxA = fmaxf(mxA, __shfl_xor_sync(0xffffffffu, mxA, 2));
            mxB = fmaxf(mxB, __shfl_xor_sync(0xffffffffu, mxB, 1));
            mxB = fmaxf(mxB, __shfl_xor_sync(0xffffffffu, mxB, 2));

            float mnA = fmaxf(m_prev[0], mxA);
            float mnB = fmaxf(m_prev[1], mxB);
            float alA = __expf(m_prev[0] - mnA);
            float alB = __expf(m_prev[1] - mnB);

            float rsA = 0.f, rsB = 0.f;
            #pragma unroll
            for (int nt = 0; nt < 8; ++nt) {
                s[nt][0] = __expf(s[nt][0] - mnA);
                s[nt][1] = __expf(s[nt][1] - mnA);
                s[nt][2] = __expf(s[nt][2] - mnB);
                s[nt][3] = __expf(s[nt][3] - mnB);
                rsA += s[nt][0] + s[nt][1];
                rsB += s[nt][2] + s[nt][3];
            }
            rsA += __shfl_xor_sync(0xffffffffu, rsA, 1);
            rsA += __shfl_xor_sync(0xffffffffu, rsA, 2);
            rsB += __shfl_xor_sync(0xffffffffu, rsB, 1);
            rsB += __shfl_xor_sync(0xffffffffu, rsB, 2);

            lsum[0] = lsum[0] * alA + rsA;
            lsum[1] = lsum[1] * alB + rsB;
            m_prev[0] = mnA;
            m_prev[1] = mnB;

            #pragma unroll
            for (int nt = 0; nt < 8; ++nt) {
                o[nt][0] *= alA; o[nt][1] *= alA;
                o[nt][2] *= alB; o[nt][3] *= alB;
            }
        }

        // ---- O += P V : P directly from accumulators (FA2 layout reuse) ----
        {
            const unsigned* Vw = reinterpret_cast<const unsigned*>(sm.VT[cur]);
            #pragma unroll
            for (int kt = 0; kt < 4; ++kt) {
                unsigned a0 = packf2(s[2*kt][0],   s[2*kt][1]);
                unsigned a1 = packf2(s[2*kt][2],   s[2*kt][3]);
                unsigned a2 = packf2(s[2*kt+1][0], s[2*kt+1][1]);
                unsigned a3 = packf2(s[2*kt+1][2], s[2*kt+1][3]);
                #pragma unroll
                for (int nt = 0; nt < 8; ++nt) {
                    unsigned b0 = Vw[(nt * 8 + g) * LDW + kt * 8 + tg];
                    unsigned b1 = Vw[(nt * 8 + g) * LDW + kt * 8 + tg + 4];
                    hmma(o[nt], a0, a1, a2, a3, b0, b1);
                }
            }
        }

        if (c + 1 < 32) STORE_KVM((c + 1) & 1);
        __syncthreads();
    }

    // ---- epilogue ----
    float iA = 1.f / lsum[0];
    float iB = 1.f / lsum[1];
    #pragma unroll
    for (int nt = 0; nt < 8; ++nt) {
        int col = nt * 8 + 2 * tg;
        *reinterpret_cast<float2*>(
            out + ((size_t)b * SEQ + i0 + r0 + g) * DHEAD + col)
            = make_float2(o[nt][0] * iA, o[nt][1] * iA);
        *reinterpret_cast<float2*>(
            out + ((size_t)b * SEQ + i0 + r0 + g + 8) * DHEAD + col)
            = make_float2(o[nt][2] * iB, o[nt][3] * iB);
    }
    #undef LOAD_KVM
    #undef STORE_KVM
}

// ---------------------------------------------------------------------------
extern "C" void kernel_launch(void* const* d_in, const int* in_sizes, int n_in,
                              void* d_out, int out_size)
{
    const void*  mask = nullptr;
    const float* x    = nullptr;
    const float* wbuf[3] = {nullptr, nullptr, nullptr};
    int nw = 0;

    for (int i = 0; i < n_in; ++i) {
        size_t sz = (size_t)in_sizes[i];
        if (sz == MASK_ELEMS)      mask = d_in[i];
        else if (sz == X_ELEMS)    x = (const float*)d_in[i];
        else if (sz == W_ELEMS && nw < 3) wbuf[nw++] = (const float*)d_in[i];
    }
    const float* wk = wbuf[0];
    const float* wq = wbuf[1];
    const float* wv = wbuf[2];
    float* out = (float*)d_out;

    const int proj_smem = (128 * LDH + 64 * LDH) * (int)sizeof(__half);
    cudaFuncSetAttribute(proj_kernel,
                         cudaFuncAttributeMaxDynamicSharedMemorySize, proj_smem);
    proj_kernel<<<dim3(ROWS / 128, 3), 256, proj_smem>>>(x, wq, wk, wv);

    cudaFuncSetAttribute(attn_kernel,
                         cudaFuncAttributeMaxDynamicSharedMemorySize,
                         (int)sizeof(AttnSmem));
    attn_kernel<<<dim3(SEQ / 128, BATCH), 256, sizeof(AttnSmem)>>>(
        (const unsigned char*)mask, out);
}